// round 16
// baseline (speedup 1.0000x reference)
#include <cuda_runtime.h>
#include <cuda_bf16.h>
#include <stdint.h>

#define NGRID    8192
#define NLAYER   24
#define NPERIODS 50
#define NOBS     4096
#define NC       200
#define NPAD     64

#define BM       128
#define BN       64
#define BK       64
#define SPLITK   8
#define KCHUNK   (NGRID / SPLITK)    // 1024
#define NIT      (KCHUNK / BK)       // 16
#define LDA      (BK + 8)            // 72: (4g+t) bank pattern, conflict-free
#define SMEM_GEMM ((2 * BM * LDA + 2 * BN * LDA) * 2)   // 55296 bytes

// Scratch (no allocations allowed -> __device__ globals)
__device__ __align__(16) __nv_bfloat16 g_rcpBT[NPAD * NGRID];     // B^T: [n][k]
__device__ __align__(16) float         g_part[SPLITK][NOBS * NPAD];
__device__ double                      g_acc;
__device__ unsigned int                g_count;

// order-preserving float<->uint keys (valid for all signs)
__device__ __forceinline__ unsigned int fkey(float f) {
    unsigned int u = __float_as_uint(f);
    return (u & 0x80000000u) ? ~u : (u | 0x80000000u);
}
__device__ __forceinline__ float funkey(unsigned int k) {
    unsigned int u = (k & 0x80000000u) ? (k & 0x7fffffffu) : ~k;
    return __uint_as_float(u);
}

// ---------------------------------------------------------------- rcp -> B^T (bf16)
__global__ void __launch_bounds__(256) k_rcp(const float* __restrict__ Vs,
                                             const float* __restrict__ thick,
                                             const float* __restrict__ periods) {
    __shared__ float Wsh[4 * NLAYER];
    int pbase = blockIdx.y * 4;

    if (threadIdx.x < 4) {
        int p = pbase + threadIdx.x;
        float th[NLAYER], z[NLAYER];
        float cs = 0.0f;
        for (int l = 0; l < NLAYER; l++) {
            th[l] = thick[l];
            cs += th[l];
            z[l] = cs - 0.5f * th[l];
        }
        float w[NLAYER];
        if (p < NPERIODS) {
            float inv_ds = 3.0f / (3.0f * periods[p]);   // 1/(VREF*T/3), VREF=3
            float s = 0.0f;
            for (int l = 0; l < NLAYER; l++) {
                w[l] = expf(-z[l] * inv_ds) * th[l];
                s += w[l];
            }
            float inv_s = 1.0f / s;
            for (int l = 0; l < NLAYER; l++) w[l] *= inv_s;
        } else {
            for (int l = 0; l < NLAYER; l++) w[l] = 0.0f;
        }
        for (int l = 0; l < NLAYER; l++) Wsh[threadIdx.x * NLAYER + l] = w[l];
    }
    if (blockIdx.x == 0 && blockIdx.y == 0 && threadIdx.x == 0) {
        g_acc = 0.0;
        g_count = 0u;
    }
    __syncthreads();

    int gcell = blockIdx.x * 256 + threadIdx.x;

    float v[NLAYER];
    const float4* vp = (const float4*)(Vs + (size_t)gcell * NLAYER);
#pragma unroll
    for (int i = 0; i < 6; i++) {
        float4 f = vp[i];
        v[4*i+0] = f.x; v[4*i+1] = f.y; v[4*i+2] = f.z; v[4*i+3] = f.w;
    }
#pragma unroll
    for (int pp = 0; pp < 4; pp++) {
        int p = pbase + pp;
        __nv_bfloat16 out = __float2bfloat16(0.0f);
        if (p < NPERIODS) {
            const float* w = Wsh + pp * NLAYER;
            float s = 0.0f;
#pragma unroll
            for (int l = 0; l < NLAYER; l++) s += w[l] * v[l];
            out = __float2bfloat16(1.0f / (0.92f * s));
        }
        g_rcpBT[(size_t)p * NGRID + gcell] = out;   // coalesced along gcell
    }
}

// ---------------------------------------------------------------- GEMM (bf16 HMMA)
// Round-11 proven: SPLITK=8, double-buffered smem, one __syncthreads per tile-loop.
__global__ void __launch_bounds__(256, 2) k_gemm(const float* __restrict__ A) {
    extern __shared__ __align__(16) __nv_bfloat16 sm[];
    __nv_bfloat16* Asb[2] = { sm,                sm + BM * LDA };
    __nv_bfloat16* Bsb[2] = { sm + 2 * BM * LDA, sm + 2 * BM * LDA + BN * LDA };

    int tid  = threadIdx.x;
    int lane = tid & 31, warp = tid >> 5;
    int wm = warp & 3, wn = warp >> 2;          // 4 x 2 warp grid
    int g = lane >> 2, t = lane & 3;
    int mBase = blockIdx.x * BM;
    int kt0   = blockIdx.y * KCHUNK;

    float acc[2][4][4];
#pragma unroll
    for (int mt = 0; mt < 2; mt++)
#pragma unroll
        for (int nt = 0; nt < 4; nt++)
#pragma unroll
            for (int i = 0; i < 4; i++) acc[mt][nt][i] = 0.0f;

    float4 aR[8], bR[2];

#define LOAD_A(KT)                                                              \
    _Pragma("unroll")                                                           \
    for (int i = 0; i < 8; i++) {                                               \
        int f = i * 256 + tid; int row = f >> 4; int c4 = f & 15;               \
        aR[i] = *(const float4*)(A + (size_t)(mBase + row) * NGRID + (KT) + c4 * 4); \
    }
#define LOAD_B(KT)                                                              \
    _Pragma("unroll")                                                           \
    for (int i = 0; i < 2; i++) {                                               \
        int f = i * 256 + tid; int row = f >> 3; int c4 = f & 7;                \
        bR[i] = *(const float4*)((const __nv_bfloat16*)g_rcpBT + (size_t)row * NGRID + (KT) + c4 * 8); \
    }
#define STORE_AB(S)                                                             \
    _Pragma("unroll")                                                           \
    for (int i = 0; i < 8; i++) {                                               \
        int f = i * 256 + tid; int row = f >> 4; int c4 = f & 15;               \
        __nv_bfloat162 lo = __float22bfloat162_rn(make_float2(aR[i].x, aR[i].y)); \
        __nv_bfloat162 hi = __float22bfloat162_rn(make_float2(aR[i].z, aR[i].w)); \
        __nv_bfloat162* dst = (__nv_bfloat162*)&Asb[S][row * LDA + c4 * 4];     \
        dst[0] = lo; dst[1] = hi;                                               \
    }                                                                           \
    _Pragma("unroll")                                                           \
    for (int i = 0; i < 2; i++) {                                               \
        int f = i * 256 + tid; int row = f >> 3; int c4 = f & 7;                \
        *(float4*)&Bsb[S][row * LDA + c4 * 8] = bR[i];                          \
    }

    LOAD_A(kt0);
    LOAD_B(kt0);
    STORE_AB(0);
    __syncthreads();

    for (int it = 0; it < NIT; it++) {
        int cur = it & 1;
        if (it + 1 < NIT) { LOAD_A(kt0 + (it + 1) * BK); LOAD_B(kt0 + (it + 1) * BK); }

        const __nv_bfloat16* As = Asb[cur];
        const __nv_bfloat16* Bs = Bsb[cur];
#pragma unroll
        for (int kk = 0; kk < BK; kk += 16) {
            uint32_t b[4][2];
#pragma unroll
            for (int nt = 0; nt < 4; nt++) {
                const uint32_t* bp = (const uint32_t*)&Bs[(wn * 32 + nt * 8 + g) * LDA + kk];
                b[nt][0] = bp[t]; b[nt][1] = bp[t + 4];
            }
#pragma unroll
            for (int mt = 0; mt < 2; mt++) {
                int r = wm * 32 + mt * 16 + g;
                const uint32_t* a0p = (const uint32_t*)&As[r * LDA + kk];
                const uint32_t* a1p = (const uint32_t*)&As[(r + 8) * LDA + kk];
                uint32_t a0 = a0p[t], a2 = a0p[t + 4];
                uint32_t a1 = a1p[t], a3 = a1p[t + 4];
#pragma unroll
                for (int nt = 0; nt < 4; nt++) {
                    asm volatile(
                        "mma.sync.aligned.m16n8k16.row.col.f32.bf16.bf16.f32 "
                        "{%0,%1,%2,%3}, {%4,%5,%6,%7}, {%8,%9}, {%0,%1,%2,%3};\n"
                        : "+f"(acc[mt][nt][0]), "+f"(acc[mt][nt][1]),
                          "+f"(acc[mt][nt][2]), "+f"(acc[mt][nt][3])
                        : "r"(a0), "r"(a1), "r"(a2), "r"(a3),
                          "r"(b[nt][0]), "r"(b[nt][1]));
                }
            }
        }

        if (it + 1 < NIT) { STORE_AB(cur ^ 1); }
        __syncthreads();
    }

    float* out = g_part[blockIdx.y];
#pragma unroll
    for (int mt = 0; mt < 2; mt++)
#pragma unroll
        for (int nt = 0; nt < 4; nt++) {
            int r0 = mBase + wm * 32 + mt * 16 + g;
            int c  = wn * 32 + nt * 8 + t * 2;
            *(float2*)&out[(size_t)r0 * NPAD + c]       = make_float2(acc[mt][nt][0], acc[mt][nt][1]);
            *(float2*)&out[(size_t)(r0 + 8) * NPAD + c] = make_float2(acc[mt][nt][2], acc[mt][nt][3]);
        }
}

// ---------------------------------------------------------------- epilogue (block per obs)
// Round-14 body; (1) slab copy in 2 commit groups (compute half 1 while half 2
// streams); (2) the two REDUXes issue back-to-back. Macro locals renamed to
// avoid the round-15 shadowing bug.
#define ES_F4   (NPERIODS * NC / 4)      // 2500 float4s
#define HALF_F4 (ES_F4 / 2)              // 1250 (25 periods)
#define HALF_P  (NPERIODS / 2)           // 25

__global__ void __launch_bounds__(256) k_epilogue(const float* __restrict__ energy,
                                                  const float* __restrict__ c_axis,
                                                  float* __restrict__ outp) {
    int obs  = blockIdx.x;
    int tid  = threadIdx.x;
    int lane = tid & 31, warp = tid >> 5;

    __shared__ __align__(16) float es[NPERIODS * NC];   // 40 KB energy slab
    __shared__ __align__(16) float ca[NC];
    __shared__ float spred_sh[NPAD];
    __shared__ float part[8];

    const float4* src = (const float4*)(energy + (size_t)obs * NPERIODS * NC);
    uint32_t dst = (uint32_t)__cvta_generic_to_shared(es);

    // group A: periods [0,25) = float4s [0,1250)
#pragma unroll
    for (int i = 0; i < (HALF_F4 + 255) / 256; i++) {
        int idx = i * 256 + tid;
        if (idx < HALF_F4)
            asm volatile("cp.async.cg.shared.global [%0], [%1], 16;\n"
                         :: "r"(dst + idx * 16), "l"(src + idx) : "memory");
    }
    asm volatile("cp.async.commit_group;\n" ::: "memory");

    // group B: periods [25,50) = float4s [1250,2500)
#pragma unroll
    for (int i = 0; i < (HALF_F4 + 255) / 256; i++) {
        int idx = HALF_F4 + i * 256 + tid;
        if (idx < ES_F4)
            asm volatile("cp.async.cg.shared.global [%0], [%1], 16;\n"
                         :: "r"(dst + idx * 16), "l"(src + idx) : "memory");
    }
    asm volatile("cp.async.commit_group;\n" ::: "memory");

    // overlap: split-K reduce + c_axis load while both halves stream in
    if (tid < NPAD) {
        float s = 0.0f;
#pragma unroll
        for (int sk = 0; sk < SPLITK; sk++)
            s += g_part[sk][(size_t)obs * NPAD + tid];
        spred_sh[tid] = s;
    }
    if (tid >= 64 && tid < 64 + NC / 4)
        *(float4*)&ca[(tid - 64) * 4] = ((const float4*)(c_axis + (size_t)obs * NC))[tid - 64];

    float wsum = 0.0f;

#define EPI_BODY(PQ)                                                                \
    {                                                                               \
        const int pq = (PQ);                                                        \
        const float* eq = es + pq * NC;                                             \
        const float4* eq4 = (const float4*)eq;                                      \
        float4 vq = eq4[lane];                                                      \
        float mq = fmaxf(fmaxf(vq.x, vq.y), fmaxf(vq.z, vq.w));                     \
        if (lane < 18) {                                                            \
            float4 vq2 = eq4[lane + 32];                                            \
            mq = fmaxf(mq, fmaxf(fmaxf(vq2.x, vq2.y), fmaxf(vq2.z, vq2.w)));        \
        }                                                                           \
        float cpq = 1.0f / spred_sh[pq];                                            \
        float4 cq = ((const float4*)ca)[lane];                                      \
        int cntq = (cq.x < cpq) + (cq.y < cpq) + (cq.z < cpq) + (cq.w < cpq);       \
        if (lane < 18) {                                                            \
            float4 cq2 = ((const float4*)ca)[lane + 32];                            \
            cntq += (cq2.x < cpq) + (cq2.y < cpq) + (cq2.z < cpq) + (cq2.w < cpq);  \
        }                                                                           \
        int idxq = __reduce_add_sync(0xffffffffu, cntq);   /* independent...   */   \
        mq = funkey(__reduce_max_sync(0xffffffffu, fkey(mq))); /* back-to-back */   \
        idxq = min(max(idxq, 1), NC - 1);                                           \
        if (lane == 0) {                                                            \
            float c0q = ca[idxq - 1], c1q = ca[idxq];                               \
            float e0q = eq[idxq - 1], e1q = eq[idxq];                               \
            float wq = (cpq - c0q) / (c1q - c0q + 1e-12f);                          \
            wsum += mq - (e0q + wq * (e1q - e0q));                                  \
        }                                                                           \
    }

    // first half: wait only for group A (group B still streaming)
    asm volatile("cp.async.wait_group 1;\n" ::: "memory");
    __syncthreads();
    for (int p = warp; p < HALF_P; p += 8) EPI_BODY(p);

    // second half
    asm volatile("cp.async.wait_group 0;\n" ::: "memory");
    __syncthreads();
    for (int p = HALF_P + warp; p < NPERIODS; p += 8) EPI_BODY(p);

    if (lane == 0) part[warp] = wsum;
    __syncthreads();
    if (tid == 0) {
        float s = 0.0f;
        for (int i = 0; i < 8; i++) s += part[i];
        atomicAdd(&g_acc, (double)s);
        __threadfence();
        unsigned int done = atomicAdd(&g_count, 1u);
        if (done == NOBS - 1) {
            double a = *((volatile double*)&g_acc);
            outp[0] = (float)(-a);                       // SIGMA = 1.0
        }
    }
}

// ---------------------------------------------------------------- launch
extern "C" void kernel_launch(void* const* d_in, const int* in_sizes, int n_in,
                              void* d_out, int out_size) {
    const float *Vs = nullptr, *A = nullptr, *energy = nullptr,
                *c_axis = nullptr, *thick = nullptr, *periods = nullptr;
    for (int i = 0; i < n_in; i++) {
        switch (in_sizes[i]) {
            case NGRID * NLAYER:          Vs      = (const float*)d_in[i]; break;
            case NOBS * NGRID:            A       = (const float*)d_in[i]; break;
            case NOBS * NPERIODS * NC:    energy  = (const float*)d_in[i]; break;
            case NOBS * NC:               c_axis  = (const float*)d_in[i]; break;
            case NLAYER:                  thick   = (const float*)d_in[i]; break;
            case NPERIODS:                periods = (const float*)d_in[i]; break;
        }
    }

    static bool attr_set = false;
    if (!attr_set) {
        cudaFuncSetAttribute(k_gemm, cudaFuncAttributeMaxDynamicSharedMemorySize, SMEM_GEMM);
        attr_set = true;
    }

    dim3 grcp(NGRID / 256, NPAD / 4);
    k_rcp<<<grcp, 256>>>(Vs, thick, periods);

    dim3 g(NOBS / BM, SPLITK);
    k_gemm<<<g, 256, SMEM_GEMM>>>(A);

    k_epilogue<<<NOBS, 256>>>(energy, c_axis, (float*)d_out);
}

// round 17
// speedup vs baseline: 1.0458x; 1.0458x over previous
#include <cuda_runtime.h>
#include <cuda_bf16.h>
#include <stdint.h>

#define NGRID    8192
#define NLAYER   24
#define NPERIODS 50
#define NOBS     4096
#define NC       200
#define NPAD     64

#define BM       128
#define BN       64
#define BK       64
#define SPLITK   8
#define KCHUNK   (NGRID / SPLITK)    // 1024
#define NIT      (KCHUNK / BK)       // 16
#define LDA      (BK + 8)            // 72: (4g+t) bank pattern, conflict-free
#define SMEM_GEMM ((2 * BM * LDA + 2 * BN * LDA) * 2)   // 55296 bytes

// Scratch (no allocations allowed -> __device__ globals)
__device__ __align__(16) __nv_bfloat16 g_rcpBT[NPAD * NGRID];     // B^T: [n][k]
__device__ __align__(16) float         g_part[SPLITK][NOBS * NPAD];
__device__ double                      g_acc;
__device__ unsigned int                g_count;

// order-preserving float<->uint keys (valid for all signs)
__device__ __forceinline__ unsigned int fkey(float f) {
    unsigned int u = __float_as_uint(f);
    return (u & 0x80000000u) ? ~u : (u | 0x80000000u);
}
__device__ __forceinline__ float funkey(unsigned int k) {
    unsigned int u = (k & 0x80000000u) ? (k & 0x7fffffffu) : ~k;
    return __uint_as_float(u);
}

// ---------------------------------------------------------------- rcp -> B^T (bf16)
__global__ void __launch_bounds__(256) k_rcp(const float* __restrict__ Vs,
                                             const float* __restrict__ thick,
                                             const float* __restrict__ periods) {
    // allow k_gemm to launch concurrently (its A-prefetch is independent of us)
    cudaTriggerProgrammaticLaunchCompletion();

    __shared__ float Wsh[4 * NLAYER];
    int pbase = blockIdx.y * 4;

    if (threadIdx.x < 4) {
        int p = pbase + threadIdx.x;
        float th[NLAYER], z[NLAYER];
        float cs = 0.0f;
        for (int l = 0; l < NLAYER; l++) {
            th[l] = thick[l];
            cs += th[l];
            z[l] = cs - 0.5f * th[l];
        }
        float w[NLAYER];
        if (p < NPERIODS) {
            float inv_ds = 3.0f / (3.0f * periods[p]);   // 1/(VREF*T/3), VREF=3
            float s = 0.0f;
            for (int l = 0; l < NLAYER; l++) {
                w[l] = expf(-z[l] * inv_ds) * th[l];
                s += w[l];
            }
            float inv_s = 1.0f / s;
            for (int l = 0; l < NLAYER; l++) w[l] *= inv_s;
        } else {
            for (int l = 0; l < NLAYER; l++) w[l] = 0.0f;
        }
        for (int l = 0; l < NLAYER; l++) Wsh[threadIdx.x * NLAYER + l] = w[l];
    }
    if (blockIdx.x == 0 && blockIdx.y == 0 && threadIdx.x == 0) {
        g_acc = 0.0;
        g_count = 0u;
    }
    __syncthreads();

    int gcell = blockIdx.x * 256 + threadIdx.x;

    float v[NLAYER];
    const float4* vp = (const float4*)(Vs + (size_t)gcell * NLAYER);
#pragma unroll
    for (int i = 0; i < 6; i++) {
        float4 f = vp[i];
        v[4*i+0] = f.x; v[4*i+1] = f.y; v[4*i+2] = f.z; v[4*i+3] = f.w;
    }
#pragma unroll
    for (int pp = 0; pp < 4; pp++) {
        int p = pbase + pp;
        __nv_bfloat16 out = __float2bfloat16(0.0f);
        if (p < NPERIODS) {
            const float* w = Wsh + pp * NLAYER;
            float s = 0.0f;
#pragma unroll
            for (int l = 0; l < NLAYER; l++) s += w[l] * v[l];
            out = __float2bfloat16(1.0f / (0.92f * s));
        }
        g_rcpBT[(size_t)p * NGRID + gcell] = out;   // coalesced along gcell
    }
}

// ---------------------------------------------------------------- GEMM (bf16 HMMA)
// Round-11 proven loop. PDL: trigger at entry (lets epilogue co-launch),
// grid-dependency sync between the independent A-prefetch and the rcp-dependent B load.
__global__ void __launch_bounds__(256, 2) k_gemm(const float* __restrict__ A) {
    cudaTriggerProgrammaticLaunchCompletion();

    extern __shared__ __align__(16) __nv_bfloat16 sm[];
    __nv_bfloat16* Asb[2] = { sm,                sm + BM * LDA };
    __nv_bfloat16* Bsb[2] = { sm + 2 * BM * LDA, sm + 2 * BM * LDA + BN * LDA };

    int tid  = threadIdx.x;
    int lane = tid & 31, warp = tid >> 5;
    int wm = warp & 3, wn = warp >> 2;          // 4 x 2 warp grid
    int g = lane >> 2, t = lane & 3;
    int mBase = blockIdx.x * BM;
    int kt0   = blockIdx.y * KCHUNK;

    float acc[2][4][4];
#pragma unroll
    for (int mt = 0; mt < 2; mt++)
#pragma unroll
        for (int nt = 0; nt < 4; nt++)
#pragma unroll
            for (int i = 0; i < 4; i++) acc[mt][nt][i] = 0.0f;

    float4 aR[8], bR[2];

#define LOAD_A(KT)                                                              \
    _Pragma("unroll")                                                           \
    for (int i = 0; i < 8; i++) {                                               \
        int f = i * 256 + tid; int row = f >> 4; int c4 = f & 15;               \
        aR[i] = *(const float4*)(A + (size_t)(mBase + row) * NGRID + (KT) + c4 * 4); \
    }
#define LOAD_B(KT)                                                              \
    _Pragma("unroll")                                                           \
    for (int i = 0; i < 2; i++) {                                               \
        int f = i * 256 + tid; int row = f >> 3; int c4 = f & 7;                \
        bR[i] = *(const float4*)((const __nv_bfloat16*)g_rcpBT + (size_t)row * NGRID + (KT) + c4 * 8); \
    }
#define STORE_AB(S)                                                             \
    _Pragma("unroll")                                                           \
    for (int i = 0; i < 8; i++) {                                               \
        int f = i * 256 + tid; int row = f >> 4; int c4 = f & 15;               \
        __nv_bfloat162 lo = __float22bfloat162_rn(make_float2(aR[i].x, aR[i].y)); \
        __nv_bfloat162 hi = __float22bfloat162_rn(make_float2(aR[i].z, aR[i].w)); \
        __nv_bfloat162* dst = (__nv_bfloat162*)&Asb[S][row * LDA + c4 * 4];     \
        dst[0] = lo; dst[1] = hi;                                               \
    }                                                                           \
    _Pragma("unroll")                                                           \
    for (int i = 0; i < 2; i++) {                                               \
        int f = i * 256 + tid; int row = f >> 3; int c4 = f & 7;                \
        *(float4*)&Bsb[S][row * LDA + c4 * 8] = bR[i];                          \
    }

    LOAD_A(kt0);                       // independent of k_rcp -> overlaps it
    cudaGridDependencySynchronize();   // wait for k_rcp (g_rcpBT ready)
    LOAD_B(kt0);
    STORE_AB(0);
    __syncthreads();

    for (int it = 0; it < NIT; it++) {
        int cur = it & 1;
        if (it + 1 < NIT) { LOAD_A(kt0 + (it + 1) * BK); LOAD_B(kt0 + (it + 1) * BK); }

        const __nv_bfloat16* As = Asb[cur];
        const __nv_bfloat16* Bs = Bsb[cur];
#pragma unroll
        for (int kk = 0; kk < BK; kk += 16) {
            uint32_t b[4][2];
#pragma unroll
            for (int nt = 0; nt < 4; nt++) {
                const uint32_t* bp = (const uint32_t*)&Bs[(wn * 32 + nt * 8 + g) * LDA + kk];
                b[nt][0] = bp[t]; b[nt][1] = bp[t + 4];
            }
#pragma unroll
            for (int mt = 0; mt < 2; mt++) {
                int r = wm * 32 + mt * 16 + g;
                const uint32_t* a0p = (const uint32_t*)&As[r * LDA + kk];
                const uint32_t* a1p = (const uint32_t*)&As[(r + 8) * LDA + kk];
                uint32_t a0 = a0p[t], a2 = a0p[t + 4];
                uint32_t a1 = a1p[t], a3 = a1p[t + 4];
#pragma unroll
                for (int nt = 0; nt < 4; nt++) {
                    asm volatile(
                        "mma.sync.aligned.m16n8k16.row.col.f32.bf16.bf16.f32 "
                        "{%0,%1,%2,%3}, {%4,%5,%6,%7}, {%8,%9}, {%0,%1,%2,%3};\n"
                        : "+f"(acc[mt][nt][0]), "+f"(acc[mt][nt][1]),
                          "+f"(acc[mt][nt][2]), "+f"(acc[mt][nt][3])
                        : "r"(a0), "r"(a1), "r"(a2), "r"(a3),
                          "r"(b[nt][0]), "r"(b[nt][1]));
                }
            }
        }

        if (it + 1 < NIT) { STORE_AB(cur ^ 1); }
        __syncthreads();
    }

    float* out = g_part[blockIdx.y];
#pragma unroll
    for (int mt = 0; mt < 2; mt++)
#pragma unroll
        for (int nt = 0; nt < 4; nt++) {
            int r0 = mBase + wm * 32 + mt * 16 + g;
            int c  = wn * 32 + nt * 8 + t * 2;
            *(float2*)&out[(size_t)r0 * NPAD + c]       = make_float2(acc[mt][nt][0], acc[mt][nt][1]);
            *(float2*)&out[(size_t)(r0 + 8) * NPAD + c] = make_float2(acc[mt][nt][2], acc[mt][nt][3]);
        }
}

// ---------------------------------------------------------------- epilogue (block per obs)
// Round-14 proven body. PDL: energy cp.async + c_axis load (independent of gemm)
// issue first; grid-dependency sync gates only the g_part reduce.
#define ES_F4 (NPERIODS * NC / 4)    // 2500 float4s = 40000 B

__global__ void __launch_bounds__(256) k_epilogue(const float* __restrict__ energy,
                                                  const float* __restrict__ c_axis,
                                                  float* __restrict__ outp) {
    int obs  = blockIdx.x;
    int tid  = threadIdx.x;
    int lane = tid & 31, warp = tid >> 5;

    __shared__ __align__(16) float es[NPERIODS * NC];   // 40 KB energy slab
    __shared__ __align__(16) float ca[NC];
    __shared__ float spred_sh[NPAD];
    __shared__ float part[8];

    // ---- independent prologue: burst-issue energy copy + c_axis load ----
    {
        const float4* src = (const float4*)(energy + (size_t)obs * NPERIODS * NC);
        uint32_t dst = (uint32_t)__cvta_generic_to_shared(es);
#pragma unroll
        for (int i = 0; i < (ES_F4 + 255) / 256; i++) {      // 10 iters, last partial
            int idx = i * 256 + tid;
            if (idx < ES_F4) {
                asm volatile("cp.async.cg.shared.global [%0], [%1], 16;\n"
                             :: "r"(dst + idx * 16), "l"(src + idx) : "memory");
            }
        }
        asm volatile("cp.async.commit_group;\n" ::: "memory");
    }
    if (tid >= 64 && tid < 64 + NC / 4)
        *(float4*)&ca[(tid - 64) * 4] = ((const float4*)(c_axis + (size_t)obs * NC))[tid - 64];

    // ---- wait for k_gemm completion, then the dependent g_part reduce ----
    cudaGridDependencySynchronize();

    if (tid < NPAD) {
        float s = 0.0f;
#pragma unroll
        for (int sk = 0; sk < SPLITK; sk++)
            s += g_part[sk][(size_t)obs * NPAD + tid];
        spred_sh[tid] = s;
    }

    asm volatile("cp.async.wait_group 0;\n" ::: "memory");
    __syncthreads();

    float wsum = 0.0f;
    for (int p = warp; p < NPERIODS; p += 8) {
        const float* e = es + p * NC;                    // smem row
        const float4* e4 = (const float4*)e;
        float4 v = e4[lane];
        float m = fmaxf(fmaxf(v.x, v.y), fmaxf(v.z, v.w));
        if (lane < 18) {
            float4 v2 = e4[lane + 32];
            m = fmaxf(m, fmaxf(fmaxf(v2.x, v2.y), fmaxf(v2.z, v2.w)));
        }
        // single REDUX.UMAX replaces the 5-deep SHFL chain
        m = funkey(__reduce_max_sync(0xffffffffu, fkey(m)));

        float cp = 1.0f / spred_sh[p];

        float4 c = ((const float4*)ca)[lane];
        int cnt = (c.x < cp) + (c.y < cp) + (c.z < cp) + (c.w < cp);
        if (lane < 18) {
            float4 c2 = ((const float4*)ca)[lane + 32];
            cnt += (c2.x < cp) + (c2.y < cp) + (c2.z < cp) + (c2.w < cp);
        }
        int idx = __reduce_add_sync(0xffffffffu, cnt);   // searchsorted-left
        idx = min(max(idx, 1), NC - 1);

        if (lane == 0) {
            float c0 = ca[idx - 1], c1 = ca[idx];
            float e0 = e[idx - 1],  e1 = e[idx];        // smem gather
            float w = (cp - c0) / (c1 - c0 + 1e-12f);
            wsum += m - (e0 + w * (e1 - e0));
        }
    }

    if (lane == 0) part[warp] = wsum;
    __syncthreads();
    if (tid == 0) {
        float s = 0.0f;
        for (int i = 0; i < 8; i++) s += part[i];
        atomicAdd(&g_acc, (double)s);
        __threadfence();
        unsigned int done = atomicAdd(&g_count, 1u);
        if (done == NOBS - 1) {
            double a = *((volatile double*)&g_acc);
            outp[0] = (float)(-a);                       // SIGMA = 1.0
        }
    }
}

// ---------------------------------------------------------------- launch
extern "C" void kernel_launch(void* const* d_in, const int* in_sizes, int n_in,
                              void* d_out, int out_size) {
    const float *Vs = nullptr, *A = nullptr, *energy = nullptr,
                *c_axis = nullptr, *thick = nullptr, *periods = nullptr;
    for (int i = 0; i < n_in; i++) {
        switch (in_sizes[i]) {
            case NGRID * NLAYER:          Vs      = (const float*)d_in[i]; break;
            case NOBS * NGRID:            A       = (const float*)d_in[i]; break;
            case NOBS * NPERIODS * NC:    energy  = (const float*)d_in[i]; break;
            case NOBS * NC:               c_axis  = (const float*)d_in[i]; break;
            case NLAYER:                  thick   = (const float*)d_in[i]; break;
            case NPERIODS:                periods = (const float*)d_in[i]; break;
        }
    }

    static bool attr_set = false;
    if (!attr_set) {
        cudaFuncSetAttribute(k_gemm, cudaFuncAttributeMaxDynamicSharedMemorySize, SMEM_GEMM);
        attr_set = true;
    }

    dim3 grcp(NGRID / 256, NPAD / 4);
    k_rcp<<<grcp, 256>>>(Vs, thick, periods);

    // k_gemm with programmatic dependent launch (fallback: plain launch)
    {
        cudaLaunchAttribute at[1];
        at[0].id = cudaLaunchAttributeProgrammaticStreamSerialization;
        at[0].val.programmaticStreamSerializationAllowed = 1;
        cudaLaunchConfig_t cfg = {};
        cfg.gridDim  = dim3(NOBS / BM, SPLITK);
        cfg.blockDim = dim3(256);
        cfg.dynamicSmemBytes = SMEM_GEMM;
        cfg.stream = 0;
        cfg.attrs = at;
        cfg.numAttrs = 1;
        if (cudaLaunchKernelEx(&cfg, k_gemm, A) != cudaSuccess) {
            dim3 g(NOBS / BM, SPLITK);
            k_gemm<<<g, 256, SMEM_GEMM>>>(A);
        }
    }

    // k_epilogue with programmatic dependent launch (fallback: plain launch)
    {
        cudaLaunchAttribute at[1];
        at[0].id = cudaLaunchAttributeProgrammaticStreamSerialization;
        at[0].val.programmaticStreamSerializationAllowed = 1;
        cudaLaunchConfig_t cfg = {};
        cfg.gridDim  = dim3(NOBS);
        cfg.blockDim = dim3(256);
        cfg.dynamicSmemBytes = 0;
        cfg.stream = 0;
        cfg.attrs = at;
        cfg.numAttrs = 1;
        if (cudaLaunchKernelEx(&cfg, k_epilogue, energy, c_axis, (float*)d_out) != cudaSuccess) {
            k_epilogue<<<NOBS, 256>>>(energy, c_axis, (float*)d_out);
        }
    }
}